// round 9
// baseline (speedup 1.0000x reference)
#include <cuda_runtime.h>
#include <cstdint>

#define EPSF 1e-20f

#define Wn 256
#define OWn 511
#define IMG_IN  65536      // 256*256
#define IMG_OUT 261121     // 511*511
#define TOT_OUT 66846976   // 8*32*511*511

__device__ __forceinline__ float frcp(float x) {
    float r;
    asm("rcp.approx.f32 %0, %1;" : "=f"(r) : "f"(x));
    return r;
}

struct Consts {
    float w00, w01, w02, w10, w11, w12, w20, w21, w22;
    float i_ee, i_eo, i_oe, i_oo, bias;
};

// Full thread u (tx=0..62): input cols [4u, 4u+5] of rows {r, r+1},
// writes output cols [S0+8u, S0+8u+8) of row 2r and [S1+8u, S1+8u+8) of
// row 2r+1, both 16B-aligned. S1 = (S0+1)&3.
// Output col ox, j=ox>>1, local k=j-4u:
//   even row: even ox -> w11*c[k];           odd ox -> w10*c[k+1] + w12*c[k]
//   odd  row: even ox -> w01*cE[k]+w21*cA[k]; odd ox -> w00*cE[k+1]+w02*cE[k]+w20*cA[k+1]+w22*cA[k]
template <int S0>
__device__ __forceinline__ void full_body(
    const float (&cA)[6], const float (&pA)[6],
    const float (&cE)[6], const float (&pE)[6],
    const Consts& K, bool hasR,
    float* __restrict__ outD, float* __restrict__ outC,
    long off0, long off1) {
    // ---- even output row (uses row A only) ----
    {
        float4 vD, vC;
#define EV(i, lane)                                                          \
        { constexpr int k = (S0 + (i)) >> 1;                                 \
          if constexpr (((S0 + (i)) & 1) == 0) {                             \
              const float den = cA[k] * K.w11;                               \
              vD.lane = (pA[k] * K.w11) * frcp(den + EPSF) + K.bias;         \
              vC.lane = den * K.i_ee;                                        \
          } else {                                                           \
              const float den = fmaf(cA[k + 1], K.w10, cA[k] * K.w12);       \
              vD.lane = fmaf(pA[k + 1], K.w10, pA[k] * K.w12) *              \
                        frcp(den + EPSF) + K.bias;                           \
              vC.lane = den * K.i_eo;                                        \
          } }
        EV(0, x) EV(1, y) EV(2, z) EV(3, w)
        __stcs(reinterpret_cast<float4*>(outD + off0), vD);
        __stcs(reinterpret_cast<float4*>(outC + off0), vC);
        EV(4, x) EV(5, y) EV(6, z) EV(7, w)
        __stcs(reinterpret_cast<float4*>(outD + off0 + 4), vD);
        __stcs(reinterpret_cast<float4*>(outC + off0 + 4), vC);
#undef EV
    }
    // ---- odd output row (rows A=ky2 and E=ky0) ----
    if (hasR) {
        constexpr int S1 = (S0 + 1) & 3;
        float4 vD, vC;
#define OD(i, lane)                                                          \
        { constexpr int k = (S1 + (i)) >> 1;                                 \
          if constexpr (((S1 + (i)) & 1) == 0) {                             \
              const float den = fmaf(cE[k], K.w01, cA[k] * K.w21);           \
              vD.lane = fmaf(pE[k], K.w01, pA[k] * K.w21) *                  \
                        frcp(den + EPSF) + K.bias;                           \
              vC.lane = den * K.i_oe;                                        \
          } else {                                                           \
              const float den = fmaf(cE[k + 1], K.w00, fmaf(cE[k], K.w02,    \
                                fmaf(cA[k + 1], K.w20, cA[k] * K.w22)));     \
              vD.lane = fmaf(pE[k + 1], K.w00, fmaf(pE[k], K.w02,            \
                        fmaf(pA[k + 1], K.w20, pA[k] * K.w22))) *            \
                        frcp(den + EPSF) + K.bias;                           \
              vC.lane = den * K.i_oo;                                        \
          } }
        OD(0, x) OD(1, y) OD(2, z) OD(3, w)
        __stcs(reinterpret_cast<float4*>(outD + off1), vD);
        __stcs(reinterpret_cast<float4*>(outC + off1), vC);
        OD(4, x) OD(5, y) OD(6, z) OD(7, w)
        __stcs(reinterpret_cast<float4*>(outD + off1 + 4), vD);
        __stcs(reinterpret_cast<float4*>(outC + off1 + 4), vC);
#undef OD
    }
}

__global__ __launch_bounds__(256, 4) void deconv_kernel(
    const float* __restrict__ din,
    const float* __restrict__ cin,
    const float* __restrict__ swraw,
    const float* __restrict__ bsrc,
    float* __restrict__ out) {
    __shared__ float s_c[14];
    const int z  = blockIdx.z;
    const int ch = z & 31;
    const int tid = threadIdx.y * 64 + threadIdx.x;

    // per-block channel constants: softplus weights, parity reciprocals, bias
    if (tid < 9) {
        const float x = swraw[ch * 9 + tid];
        s_c[tid] = (x > 20.0f) ? x : log1pf(expf(x));
    }
    if (tid == 9) s_c[13] = bsrc[ch];
    __syncthreads();
    if (tid < 4) {
        float v;
        if (tid == 0)      v = s_c[4];
        else if (tid == 1) v = s_c[3] + s_c[5];
        else if (tid == 2) v = s_c[1] + s_c[7];
        else               v = s_c[0] + s_c[2] + s_c[6] + s_c[8];
        s_c[9 + tid] = 1.0f / (v + EPSF);
    }
    __syncthreads();

    Consts K;
    K.w00 = s_c[0]; K.w01 = s_c[1]; K.w02 = s_c[2];
    K.w10 = s_c[3]; K.w11 = s_c[4]; K.w12 = s_c[5];
    K.w20 = s_c[6]; K.w21 = s_c[7]; K.w22 = s_c[8];
    K.i_ee = s_c[9]; K.i_eo = s_c[10]; K.i_oe = s_c[11]; K.i_oo = s_c[12];
    K.bias = s_c[13];

    const int tx = threadIdx.x;                 // 0..63
    const int r  = blockIdx.y * 4 + threadIdx.y;  // 0..255
    const int s0 = (4 - ((z + 2 * r) & 3)) & 3;
    const int s1 = (s0 + 1) & 3;
    const bool hasR = (r < 255);
    const long base0 = (long)z * IMG_OUT + (long)(2 * r) * OWn;
    const float* dp = din + (long)z * IMG_IN;
    const float* cp = cin + (long)z * IMG_IN;
    float* outD = out;
    float* outC = out + TOT_OUT;

    if (tx < 63) {
        const int rowA = r * Wn + 4 * tx;
        const int rowB = rowA + Wn;
        const float4 dA4 = *reinterpret_cast<const float4*>(dp + rowA);
        const float2 dA2 = *reinterpret_cast<const float2*>(dp + rowA + 4);
        const float4 cA4 = *reinterpret_cast<const float4*>(cp + rowA);
        const float2 cA2 = *reinterpret_cast<const float2*>(cp + rowA + 4);
        float4 dE4 = make_float4(0.f, 0.f, 0.f, 0.f), cE4 = dE4;
        float2 dE2 = make_float2(0.f, 0.f), cE2 = dE2;
        if (hasR) {
            dE4 = *reinterpret_cast<const float4*>(dp + rowB);
            dE2 = *reinterpret_cast<const float2*>(dp + rowB + 4);
            cE4 = *reinterpret_cast<const float4*>(cp + rowB);
            cE2 = *reinterpret_cast<const float2*>(cp + rowB + 4);
        }
        const float cA[6] = {cA4.x, cA4.y, cA4.z, cA4.w, cA2.x, cA2.y};
        const float pA[6] = {cA4.x * dA4.x, cA4.y * dA4.y, cA4.z * dA4.z,
                             cA4.w * dA4.w, cA2.x * dA2.x, cA2.y * dA2.y};
        const float cE[6] = {cE4.x, cE4.y, cE4.z, cE4.w, cE2.x, cE2.y};
        const float pE[6] = {cE4.x * dE4.x, cE4.y * dE4.y, cE4.z * dE4.z,
                             cE4.w * dE4.w, cE2.x * dE2.x, cE2.y * dE2.y};

        const long off0 = base0 + s0 + 8 * tx;        // 16B aligned
        const long off1 = base0 + OWn + s1 + 8 * tx;  // 16B aligned
        switch (s0) {  // warp-uniform
        case 0:  full_body<0>(cA, pA, cE, pE, K, hasR, outD, outC, off0, off1); break;
        case 1:  full_body<1>(cA, pA, cE, pE, K, hasR, outD, outC, off0, off1); break;
        case 2:  full_body<2>(cA, pA, cE, pE, K, hasR, outD, outC, off0, off1); break;
        default: full_body<3>(cA, pA, cE, pE, K, hasR, outD, outC, off0, off1); break;
        }
    } else {
        // boundary lane: 7 leftover cols per output row (head [0,s) + tail [504+s,511))
        const float* dR = dp + r * Wn;
        const float* cR = cp + r * Wn;
        const float* dS = dR + Wn;  // valid only if hasR
        const float* cS = cR + Wn;
#pragma unroll
        for (int i = 0; i < 7; i++) {
            // even output row (oy = 2r)
            {
                const int ox = (i < s0) ? i : 504 + i;
                const int j = ox >> 1;
                float den, nom, rc;
                if ((ox & 1) == 0) {
                    const float c = __ldg(cR + j);
                    den = c * K.w11;
                    nom = c * __ldg(dR + j) * K.w11;
                    rc  = K.i_ee;
                } else {
                    const float c1 = __ldg(cR + j + 1), c0 = __ldg(cR + j);
                    den = c1 * K.w10 + c0 * K.w12;
                    nom = c1 * __ldg(dR + j + 1) * K.w10 + c0 * __ldg(dR + j) * K.w12;
                    rc  = K.i_eo;
                }
                const long o = base0 + ox;
                __stcs(outD + o, nom * frcp(den + EPSF) + K.bias);
                __stcs(outC + o, den * rc);
            }
            // odd output row (oy = 2r+1)
            if (hasR) {
                const int ox = (i < s1) ? i : 504 + i;
                const int j = ox >> 1;
                float den, nom, rc;
                if ((ox & 1) == 0) {
                    const float ce = __ldg(cS + j), ca = __ldg(cR + j);
                    den = ce * K.w01 + ca * K.w21;
                    nom = ce * __ldg(dS + j) * K.w01 + ca * __ldg(dR + j) * K.w21;
                    rc  = K.i_oe;
                } else {
                    const float ce1 = __ldg(cS + j + 1), ce0 = __ldg(cS + j);
                    const float ca1 = __ldg(cR + j + 1), ca0 = __ldg(cR + j);
                    den = ce1 * K.w00 + ce0 * K.w02 + ca1 * K.w20 + ca0 * K.w22;
                    nom = ce1 * __ldg(dS + j + 1) * K.w00 + ce0 * __ldg(dS + j) * K.w02 +
                          ca1 * __ldg(dR + j + 1) * K.w20 + ca0 * __ldg(dR + j) * K.w22;
                    rc  = K.i_oo;
                }
                const long o = base0 + OWn + ox;
                __stcs(outD + o, nom * frcp(den + EPSF) + K.bias);
                __stcs(outC + o, den * rc);
            }
        }
    }
}

extern "C" void kernel_launch(void* const* d_in, const int* in_sizes, int n_in,
                              void* d_out, int out_size) {
    const float* d    = (const float*)d_in[0];
    const float* cd   = (const float*)d_in[1];
    const float* sw   = (const float*)d_in[2];
    const float* bias = (const float*)d_in[3];
    float* out = (float*)d_out;

    dim3 blk(64, 4, 1);
    dim3 grd(1, 64, 256);   // 64 x-threads per row-pair, 256 rows / 4, 256 images
    deconv_kernel<<<grd, blk>>>(d, cd, sw, bias, out);
}

// round 14
// speedup vs baseline: 1.4772x; 1.4772x over previous
#include <cuda_runtime.h>
#include <cstdint>

#define EPSF 1e-20f

static const int Bn = 8, Cn = 32, Hn = 256, Wn = 256;
static const int OWn = 511;
#define IMG_IN  65536      // 256*256
#define IMG_OUT 261121     // 511*511
#define TOT_OUT 66846976   // 8*32*511*511

// Packed per-channel constants:
// [0..8]  = softplus(w) (row-major 3x3)
// [9..12] = 1/(parity-sum + EPS) for ee, eo, oe, oo
// [13]    = bias
__device__ __align__(16) float g_pack[Cn][16];

__global__ void prep_kernel(const float* __restrict__ sw,
                            const float* __restrict__ bias) {
    int c = threadIdx.x;
    if (c >= Cn) return;
    float w[9];
#pragma unroll
    for (int i = 0; i < 9; i++) {
        float x = sw[c * 9 + i];
        float s = (x > 20.0f) ? x : log1pf(expf(x));
        w[i] = s;
        g_pack[c][i] = s;
    }
    g_pack[c][9]  = 1.0f / (w[4] + EPSF);                         // ee: w11
    g_pack[c][10] = 1.0f / (w[3] + w[5] + EPSF);                  // eo: w10+w12
    g_pack[c][11] = 1.0f / (w[1] + w[7] + EPSF);                  // oe: w01+w21
    g_pack[c][12] = 1.0f / (w[0] + w[2] + w[6] + w[8] + EPSF);    // oo
    g_pack[c][13] = bias[c];
    g_pack[c][14] = 0.0f;
    g_pack[c][15] = 0.0f;
}

__device__ __forceinline__ float frcp(float x) {
    float r;
    asm("rcp.approx.f32 %0, %1;" : "=f"(r) : "f"(x));
    return r;
}

// Candidate evaluators on the local 4-col input window.
// Even output row (oy=2r, input row r only):
#define EV_D(k)  (cA[k] * w11)
#define EV_N(k)  (pA[k] * w11)
#define OD_D(k)  (fmaf(cA[(k)+1], w10, cA[k] * w12))
#define OD_N(k)  (fmaf(pA[(k)+1], w10, pA[k] * w12))
// Odd output row (oy=2r+1, input rows r ("A", ky=2) and r+1 ("E", ky=0)):
#define OE_D(k)  (fmaf(cE[k], w01, cA[k] * w21))
#define OE_N(k)  (fmaf(pE[k], w01, pA[k] * w21))
#define OO_D(k)  (fmaf(cE[(k)+1], w00, fmaf(cE[k], w02, fmaf(cA[(k)+1], w20, cA[k] * w22))))
#define OO_N(k)  (fmaf(pE[(k)+1], w00, fmaf(pE[k], w02, fmaf(pA[(k)+1], w20, pA[k] * w22))))

// Full thread t (0..126): input cols [2t, 2t+3], writes 4 ALIGNED output cols
// per row: row0 at ox = s0+4t.. , row1 at ox = s1+4t..  (s1 = (s0+1)&3).
// Boundary lane (tglob==127): the 3 leftover edge columns per row, scalar.
__global__ __launch_bounds__(256, 5) void deconv_kernel(
    const float* __restrict__ din,
    const float* __restrict__ cin,
    float* __restrict__ out) {
    const int tg = blockIdx.x * 32 + threadIdx.x;  // 0..127
    const int r  = blockIdx.y * 8 + threadIdx.y;   // 0..255
    const int z  = blockIdx.z;                     // b*C + ch
    const int ch = z & (Cn - 1);

    const float4* qp = reinterpret_cast<const float4*>(&g_pack[ch][0]);
    const float4 q0 = qp[0], q1 = qp[1], q2 = qp[2], q3 = qp[3];
    const float w00 = q0.x, w01 = q0.y, w02 = q0.z, w10 = q0.w;
    const float w11 = q1.x, w12 = q1.y, w20 = q1.z, w21 = q1.w;
    const float w22 = q2.x;
    const float i_ee = q2.y, i_eo = q2.z, i_oe = q2.w, i_oo = q3.x;
    const float bias = q3.y;

    const float* dp = din + (long)z * IMG_IN;
    const float* cp = cin + (long)z * IMG_IN;
    float* outD = out;
    float* outC = out + TOT_OUT;

    const int  s0   = (4 - ((z + 2 * r) & 3)) & 3;   // row0 misalign shift
    const int  s1   = (s0 + 1) & 3;                  // row1 shift
    const bool hasR = (r < 255);
    const long base0 = (long)z * IMG_OUT + (long)(2 * r) * OWn;

    if (tg < 127) {
        const int cb   = 2 * tg;
        const int rowA = r * Wn + cb;
        const float2 dA01 = *reinterpret_cast<const float2*>(dp + rowA);
        const float2 dA23 = *reinterpret_cast<const float2*>(dp + rowA + 2);
        const float2 cA01 = *reinterpret_cast<const float2*>(cp + rowA);
        const float2 cA23 = *reinterpret_cast<const float2*>(cp + rowA + 2);
        const float cA[4] = {cA01.x, cA01.y, cA23.x, cA23.y};
        const float pA[4] = {cA01.x * dA01.x, cA01.y * dA01.y,
                             cA23.x * dA23.x, cA23.y * dA23.y};
        float cE[4] = {0.f, 0.f, 0.f, 0.f};
        float pE[4] = {0.f, 0.f, 0.f, 0.f};
        if (hasR) {
            const int rowB = rowA + Wn;
            const float2 dE01 = *reinterpret_cast<const float2*>(dp + rowB);
            const float2 dE23 = *reinterpret_cast<const float2*>(dp + rowB + 2);
            const float2 cE01 = *reinterpret_cast<const float2*>(cp + rowB);
            const float2 cE23 = *reinterpret_cast<const float2*>(cp + rowB + 2);
            cE[0] = cE01.x; cE[1] = cE01.y; cE[2] = cE23.x; cE[3] = cE23.y;
            pE[0] = cE01.x * dE01.x; pE[1] = cE01.y * dE01.y;
            pE[2] = cE23.x * dE23.x; pE[3] = cE23.y * dE23.y;
        }

        float ed0, ed1, ed2, ed3, en0, en1, en2, en3;  // even output row
        float od0, od1, od2, od3, on0, on1, on2, on3;  // odd output row
        switch (s0) {  // warp-uniform
        case 0:  // row0: e0 o0 e1 o1   row1(s1=1): o0 e1 o1 e2
            ed0 = EV_D(0); ed1 = OD_D(0); ed2 = EV_D(1); ed3 = OD_D(1);
            en0 = EV_N(0); en1 = OD_N(0); en2 = EV_N(1); en3 = OD_N(1);
            od0 = OO_D(0); od1 = OE_D(1); od2 = OO_D(1); od3 = OE_D(2);
            on0 = OO_N(0); on1 = OE_N(1); on2 = OO_N(1); on3 = OE_N(2);
            break;
        case 1:  // row0: o0 e1 o1 e2   row1(s1=2): e1 o1 e2 o2
            ed0 = OD_D(0); ed1 = EV_D(1); ed2 = OD_D(1); ed3 = EV_D(2);
            en0 = OD_N(0); en1 = EV_N(1); en2 = OD_N(1); en3 = EV_N(2);
            od0 = OE_D(1); od1 = OO_D(1); od2 = OE_D(2); od3 = OO_D(2);
            on0 = OE_N(1); on1 = OO_N(1); on2 = OE_N(2); on3 = OO_N(2);
            break;
        case 2:  // row0: e1 o1 e2 o2   row1(s1=3): o1 e2 o2 e3
            ed0 = EV_D(1); ed1 = OD_D(1); ed2 = EV_D(2); ed3 = OD_D(2);
            en0 = EV_N(1); en1 = OD_N(1); en2 = EV_N(2); en3 = OD_N(2);
            od0 = OO_D(1); od1 = OE_D(2); od2 = OO_D(2); od3 = OE_D(3);
            on0 = OO_N(1); on1 = OE_N(2); on2 = OO_N(2); on3 = OE_N(3);
            break;
        default:  // s0=3  row0: o1 e2 o2 e3   row1(s1=0): e0 o0 e1 o1
            ed0 = OD_D(1); ed1 = EV_D(2); ed2 = OD_D(2); ed3 = EV_D(3);
            en0 = OD_N(1); en1 = EV_N(2); en2 = OD_N(2); en3 = EV_N(3);
            od0 = OE_D(0); od1 = OO_D(0); od2 = OE_D(1); od3 = OO_D(1);
            on0 = OE_N(0); on1 = OO_N(0); on2 = OE_N(1); on3 = OO_N(1);
            break;
        }

        // parity-sum reciprocals alternate with column parity
        const float rE0 = (s0 & 1) ? i_eo : i_ee;
        const float rE1 = (s0 & 1) ? i_ee : i_eo;
        const float rO0 = (s1 & 1) ? i_oo : i_oe;
        const float rO1 = (s1 & 1) ? i_oe : i_oo;

        const long off0 = base0 + s0 + 4 * tg;  // 16B aligned
        float4 vD, vC;
        vD.x = en0 * frcp(ed0 + EPSF) + bias;
        vD.y = en1 * frcp(ed1 + EPSF) + bias;
        vD.z = en2 * frcp(ed2 + EPSF) + bias;
        vD.w = en3 * frcp(ed3 + EPSF) + bias;
        vC.x = ed0 * rE0; vC.y = ed1 * rE1; vC.z = ed2 * rE0; vC.w = ed3 * rE1;
        __stcs(reinterpret_cast<float4*>(outD + off0), vD);
        __stcs(reinterpret_cast<float4*>(outC + off0), vC);

        if (hasR) {
            const long off1 = base0 + OWn + s1 + 4 * tg;  // 16B aligned
            vD.x = on0 * frcp(od0 + EPSF) + bias;
            vD.y = on1 * frcp(od1 + EPSF) + bias;
            vD.z = on2 * frcp(od2 + EPSF) + bias;
            vD.w = on3 * frcp(od3 + EPSF) + bias;
            vC.x = od0 * rO0; vC.y = od1 * rO1; vC.z = od2 * rO0; vC.w = od3 * rO1;
            __stcs(reinterpret_cast<float4*>(outD + off1), vD);
            __stcs(reinterpret_cast<float4*>(outC + off1), vC);
        }
    } else {
        // boundary lane: 3 leftover columns per output row (head [0,s) + tail)
        const float* dR = dp + r * Wn;
        const float* cR = cp + r * Wn;
        const float* dS = dR + Wn;  // valid only if hasR
        const float* cS = cR + Wn;
#pragma unroll
        for (int i = 0; i < 3; i++) {
            // even output row (oy = 2r)
            {
                const int ox = (i < s0) ? i : 508 + i;
                float den, nom, rc;
                if ((ox & 1) == 0) {
                    const int j = ox >> 1;
                    const float c = cR[j];
                    den = c * w11;
                    nom = c * dR[j] * w11;
                    rc  = i_ee;
                } else {
                    const int j = ox >> 1;
                    const float c1 = cR[j + 1], c0 = cR[j];
                    den = c1 * w10 + c0 * w12;
                    nom = c1 * dR[j + 1] * w10 + c0 * dR[j] * w12;
                    rc  = i_eo;
                }
                const long o = base0 + ox;
                __stcs(outD + o, nom * frcp(den + EPSF) + bias);
                __stcs(outC + o, den * rc);
            }
            // odd output row (oy = 2r+1)
            if (hasR) {
                const int ox = (i < s1) ? i : 508 + i;
                float den, nom, rc;
                if ((ox & 1) == 0) {
                    const int j = ox >> 1;
                    const float ce = cS[j], ca = cR[j];
                    den = ce * w01 + ca * w21;
                    nom = ce * dS[j] * w01 + ca * dR[j] * w21;
                    rc  = i_oe;
                } else {
                    const int j = ox >> 1;
                    const float ce1 = cS[j + 1], ce0 = cS[j];
                    const float ca1 = cR[j + 1], ca0 = cR[j];
                    den = ce1 * w00 + ce0 * w02 + ca1 * w20 + ca0 * w22;
                    nom = ce1 * dS[j + 1] * w00 + ce0 * dS[j] * w02 +
                          ca1 * dR[j + 1] * w20 + ca0 * dR[j] * w22;
                    rc  = i_oo;
                }
                const long o = base0 + OWn + ox;
                __stcs(outD + o, nom * frcp(den + EPSF) + bias);
                __stcs(outC + o, den * rc);
            }
        }
    }
}

extern "C" void kernel_launch(void* const* d_in, const int* in_sizes, int n_in,
                              void* d_out, int out_size) {
    const float* d    = (const float*)d_in[0];
    const float* cd   = (const float*)d_in[1];
    const float* sw   = (const float*)d_in[2];
    const float* bias = (const float*)d_in[3];
    float* out = (float*)d_out;

    prep_kernel<<<1, 32>>>(sw, bias);

    dim3 blk(32, 8, 1);
    dim3 grd(4, 32, Bn * Cn);   // 128 col-group threads, 256 rows / 8, 256 images
    deconv_kernel<<<grd, blk>>>(d, cd, out);
}